// round 17
// baseline (speedup 1.0000x reference)
#include <cuda_runtime.h>

#define T_STEPS 8192
#define MDIM    1024
#define INDIM   1024
#define XCOLS   5120
#define NCTA    128
#define NTHR    256
#define CELLS   8      // memory cells owned per CTA (1024/128)

// ---------------- scratch (static device globals; no allocation) -------------
__device__ float    g_xproj[(size_t)T_STEPS * XCOLS];   // 160 MB
__device__ float    g_h[MDIM];                           // h broadcast payload
__device__ float    g_a[MDIM];                           // a broadcast payload
__device__ unsigned g_ctr[2 * T_STEPS];                  // one slot per barrier (R7-proven)
__device__ unsigned g_epoch;                             // completed scan launches

// ---- R7-proven barrier primitives ---------------------------------------------
__device__ __forceinline__ void bar_arrive(unsigned slot) {
    asm volatile("red.release.gpu.global.add.u32 [%0], 1;"
                 :: "l"(&g_ctr[slot]) : "memory");
}
__device__ __forceinline__ void bar_wait(unsigned slot, unsigned target) {
    unsigned v;
    do {
        asm volatile("ld.acquire.gpu.global.u32 %0, [%1];"
                     : "=r"(v) : "l"(&g_ctr[slot]) : "memory");
    } while (v < target);
}

// ---- XLA-matched transcendentals ---------------------------------------------
__device__ __forceinline__ float xla_tanh(float x) {
    float xc = fminf(fmaxf(x, -9.0f), 9.0f);
    float x2 = xc * xc;
    float p = fmaf(x2, -2.76076847742355e-16f, 2.00018790482477e-13f);
    p = fmaf(x2, p, -8.60467152213735e-11f);
    p = fmaf(x2, p,  5.12229709037114e-08f);
    p = fmaf(x2, p,  1.48572235717979e-05f);
    p = fmaf(x2, p,  6.37261928875436e-04f);
    p = fmaf(x2, p,  4.89352455891786e-03f);
    float num = __fmul_rn(xc, p);
    float q = fmaf(x2, 1.19825839466702e-06f, 1.18534705686654e-04f);
    q = fmaf(x2, q, 2.26843463243900e-03f);
    q = fmaf(x2, q, 4.89352518554385e-03f);
    return (fabsf(x) < 4.0e-4f) ? x : __fdiv_rn(num, q);
}
__device__ __forceinline__ float xla_sigmoid(float x) {
    float e;
    asm("ex2.approx.f32 %0, %1;" : "=f"(e) : "f"(-x * 1.4426950408889634f));
    return __fdiv_rn(1.0f, __fadd_rn(1.0f, e));
}

// ---------------- Kernel 1: xproj = inputs @ Wx^T + bx  (NT SGEMM, fp32) -----
__global__ void __launch_bounds__(256) xproj_gemm(
    const float* __restrict__ A,
    const float* __restrict__ B,
    const float* __restrict__ bias)
{
    __shared__ float As[8][128];
    __shared__ float Bs[8][128];

    int tid = threadIdx.x;
    int tx  = tid & 15, ty = tid >> 4;
    int m0  = blockIdx.y * 128, n0 = blockIdx.x * 128;
    int lrow = tid >> 1, lk = (tid & 1) * 4;

    const float* Ap = A + (size_t)(m0 + lrow) * INDIM + lk;
    const float* Bp = B + (size_t)(n0 + lrow) * INDIM + lk;

    float acc[8][8];
#pragma unroll
    for (int i = 0; i < 8; i++)
#pragma unroll
        for (int j = 0; j < 8; j++) acc[i][j] = 0.0f;

    for (int k0 = 0; k0 < INDIM; k0 += 8) {
        float4 av = *(const float4*)(Ap + k0);
        float4 bv = *(const float4*)(Bp + k0);
        As[lk + 0][lrow] = av.x; As[lk + 1][lrow] = av.y;
        As[lk + 2][lrow] = av.z; As[lk + 3][lrow] = av.w;
        Bs[lk + 0][lrow] = bv.x; Bs[lk + 1][lrow] = bv.y;
        Bs[lk + 2][lrow] = bv.z; Bs[lk + 3][lrow] = bv.w;
        __syncthreads();
#pragma unroll
        for (int kk = 0; kk < 8; kk++) {
            float a[8], b[8];
            *(float4*)&a[0] = *(const float4*)&As[kk][ty * 8];
            *(float4*)&a[4] = *(const float4*)&As[kk][ty * 8 + 4];
            *(float4*)&b[0] = *(const float4*)&Bs[kk][tx * 8];
            *(float4*)&b[4] = *(const float4*)&Bs[kk][tx * 8 + 4];
#pragma unroll
            for (int i = 0; i < 8; i++)
#pragma unroll
                for (int j = 0; j < 8; j++) acc[i][j] += a[i] * b[j];
        }
        __syncthreads();
    }

    float bb[8];
#pragma unroll
    for (int j = 0; j < 8; j++) bb[j] = bias[n0 + tx * 8 + j];
#pragma unroll
    for (int i = 0; i < 8; i++) {
        float* crow = g_xproj + (size_t)(m0 + ty * 8 + i) * XCOLS + n0 + tx * 8;
        float4 v0 = make_float4(__fadd_rn(acc[i][0], bb[0]), __fadd_rn(acc[i][1], bb[1]),
                                __fadd_rn(acc[i][2], bb[2]), __fadd_rn(acc[i][3], bb[3]));
        float4 v1 = make_float4(__fadd_rn(acc[i][4], bb[4]), __fadd_rn(acc[i][5], bb[5]),
                                __fadd_rn(acc[i][6], bb[6]), __fadd_rn(acc[i][7], bb[7]));
        *(float4*)crow       = v0;
        *(float4*)(crow + 4) = v1;
    }
}

// ---------------- Kernel 2: persistent recurrent scan ------------------------
// 128 CTAs x 256 threads, R7 barrier. Warp w owns CELL w entirely:
// Wh rows {z,i,o,f} x cell w and Wm row w. h/a dots read DIRECTLY from L2
// into registers (no smem staging, no pre-dot syncthreads). z-row first so
// `a` publishes early; i/o/f rows overlap the A-barrier settle.
__global__ void __launch_bounds__(NTHR, 1) ulstm_scan(
    const float* __restrict__ Wh, const float* __restrict__ bh,
    const float* __restrict__ Wm, const float* __restrict__ bm,
    float* __restrict__ out)
{
    const int tid = threadIdx.x;
    const int w   = tid >> 5;
    const int l   = tid & 31;
    const int cta = blockIdx.x;
    const int cw  = cta * CELLS + w;   // this warp's cell (global index)

    const unsigned target = (*((volatile unsigned*)&g_epoch) + 1u) * (unsigned)NCTA;

    // ---- weights into registers: wa[0]=z-row, wa[1]=i, wa[2]=o, wa[3]=f ----
    float4 wa[4][8];
    {
        const int gorder[4] = {2, 0, 1, 3};   // gate memory order: i,o,z,f
#pragma unroll
        for (int r = 0; r < 4; r++) {
            const float4* src = (const float4*)(Wh + (size_t)(gorder[r] * MDIM + cw) * MDIM);
#pragma unroll
            for (int c4 = 0; c4 < 8; c4++) wa[r][c4] = src[c4 * 32 + l];
        }
    }
    float4 wmr[8];
    {
        const float4* src = (const float4*)(Wm + (size_t)cw * MDIM);
#pragma unroll
        for (int c4 = 0; c4 < 8; c4++) wmr[c4] = src[c4 * 32 + l];
    }
    // lane-0 per-cell scalars (cell w state lives in warp w)
    float bhz = 0.f, bhi = 0.f, bho = 0.f, bhf = 0.f, bmw = 0.f;
    float c_r = 0.f, tc_r = 0.f;
    if (l == 0) {
        bhi = bh[cw];            bho = bh[MDIM + cw];
        bhz = bh[2 * MDIM + cw]; bhf = bh[3 * MDIM + cw];
        bmw = bm[cw];
    }
    // xproj prefetch: lane g (g<5) of warp w holds gate g for cell w, one step ahead
    float xg_pre = 0.f;
    if (l < 5) xg_pre = __ldcg(g_xproj + (size_t)l * MDIM + cw);
    __syncthreads();

    const float4* gh4 = (const float4*)g_h;
    const float4* ga4 = (const float4*)g_a;

    for (int t = 0; t < T_STEPS; t++) {
        const float xg_use = xg_pre;
        if (l < 5) {
            int tn = (t + 1 < T_STEPS) ? t + 1 : t;
            xg_pre = __ldcg(g_xproj + (size_t)tn * XCOLS + (size_t)l * MDIM + cw);
        }
        // prefetch the barrier counter line ~32 steps ahead (kills cold-L2 spikes)
        if (tid == 32) {
            int pf = 2 * t + 64;
            if (pf < 2 * T_STEPS) {
                unsigned tmp;
                asm volatile("ld.global.cg.u32 %0, [%1];" : "=r"(tmp) : "l"(&g_ctr[pf]));
            }
        }

        // ---------- h -> registers (per-warp, direct from L2; no sync) -------
        float4 hv[8];
        float dz = 0.f;
        if (t > 0) {
#pragma unroll
            for (int c4 = 0; c4 < 8; c4++) hv[c4] = __ldcg(gh4 + c4 * 32 + l);
            // z-row dot FIRST
#pragma unroll
            for (int c4 = 0; c4 < 8; c4++)
                dz += wa[0][c4].x * hv[c4].x + wa[0][c4].y * hv[c4].y + wa[0][c4].z * hv[c4].z + wa[0][c4].w * hv[c4].w;
#pragma unroll
            for (int off = 16; off > 0; off >>= 1)
                dz += __shfl_xor_sync(0xffffffffu, dz, off);
        }
        float zx = __shfl_sync(0xffffffffu, xg_use, 2);
        if (l == 0) {
            float hpz = __fadd_rn(dz, bhz);                       // t==0: 0+bh == bh
            float z   = xla_sigmoid(__fadd_rn(zx, hpz));
            __stcg(&g_a[cw], __fmul_rn(z, tc_r));
        }
        __syncthreads();                 // all warps' a stores before arrival
        if (tid == 0) bar_arrive(2 * t);

        // ---------- i/o/f rows from the SAME h regs (overlap barrier settle) -
        float d0 = 0.f, d1 = 0.f, d2 = 0.f;
        if (t > 0) {
#pragma unroll
            for (int c4 = 0; c4 < 8; c4++) {
                d0 += wa[1][c4].x * hv[c4].x + wa[1][c4].y * hv[c4].y + wa[1][c4].z * hv[c4].z + wa[1][c4].w * hv[c4].w;
                d1 += wa[2][c4].x * hv[c4].x + wa[2][c4].y * hv[c4].y + wa[2][c4].z * hv[c4].z + wa[2][c4].w * hv[c4].w;
                d2 += wa[3][c4].x * hv[c4].x + wa[3][c4].y * hv[c4].y + wa[3][c4].z * hv[c4].z + wa[3][c4].w * hv[c4].w;
            }
#pragma unroll
            for (int off = 16; off > 0; off >>= 1) {
                d0 += __shfl_xor_sync(0xffffffffu, d0, off);
                d1 += __shfl_xor_sync(0xffffffffu, d1, off);
                d2 += __shfl_xor_sync(0xffffffffu, d2, off);
            }
        }
        float ix_ = __shfl_sync(0xffffffffu, xg_use, 0);
        float ox_ = __shfl_sync(0xffffffffu, xg_use, 1);
        float fx_ = __shfl_sync(0xffffffffu, xg_use, 3);
        float ux_ = __shfl_sync(0xffffffffu, xg_use, 4);
        float gi = 0.f, go = 0.f, gf = 0.f;
        if (l == 0) {
            gi = xla_sigmoid(__fadd_rn(ix_, __fadd_rn(d0, bhi)));
            go = xla_sigmoid(__fadd_rn(ox_, __fadd_rn(d1, bho)));
            gf = xla_sigmoid(__fadd_rn(fx_, __fadd_rn(d2, bhf)));
        }
        if (tid == 0) bar_wait(2 * t, target);
        __syncthreads();

        // ---------- Phase B: a -> registers (direct from L2); dot; update ----
        float acc = 0.f;
#pragma unroll
        for (int c4 = 0; c4 < 8; c4++) {
            float4 av = __ldcg(ga4 + c4 * 32 + l);
            acc += wmr[c4].x * av.x + wmr[c4].y * av.y + wmr[c4].z * av.z + wmr[c4].w * av.w;
        }
#pragma unroll
        for (int off = 16; off > 0; off >>= 1)
            acc += __shfl_xor_sync(0xffffffffu, acc, off);

        if (l == 0) {
            float u  = xla_tanh(__fadd_rn(__fadd_rn(ux_, acc), bmw));
            float c2 = __fadd_rn(__fmul_rn(gi, u), __fmul_rn(gf, c_r));
            float th = xla_tanh(c2);
            float h2 = __fmul_rn(go, th);
            c_r  = c2;
            tc_r = th;    // reused next step: a = z * tanh(c)
            if (t == T_STEPS - 1) {
                out[cw]        = c2;
                out[MDIM + cw] = h2;
            } else {
                __stcg(&g_h[cw], h2);
            }
        }
        __syncthreads();   // order all warps' h stores before the release arrival
        if (t < T_STEPS - 1) {
            if (tid == 0) {
                bar_arrive(2 * t + 1);
                bar_wait(2 * t + 1, target);
            }
            __syncthreads();
        }
    }

    // one epoch bump per launch (every CTA read g_epoch before its first
    // barrier; replays are stream-ordered; counters stay monotonic, no resets)
    if (cta == 0 && tid == 0)
        asm volatile("red.relaxed.gpu.global.add.u32 [%0], 1;" :: "l"(&g_epoch) : "memory");
}

// ---------------- launch ------------------------------------------------------
extern "C" void kernel_launch(void* const* d_in, const int* in_sizes, int n_in,
                              void* d_out, int out_size)
{
    const float* inputs = (const float*)d_in[0];
    const float* Wx     = (const float*)d_in[1];
    const float* bx     = (const float*)d_in[2];
    const float* Wh     = (const float*)d_in[3];
    const float* bh     = (const float*)d_in[4];
    const float* Wm     = (const float*)d_in[5];
    const float* bm     = (const float*)d_in[6];
    float* out = (float*)d_out;

    dim3 ggrid(XCOLS / 128, T_STEPS / 128);   // (40, 64)
    xproj_gemm<<<ggrid, 256>>>(inputs, Wx, bx);

    ulstm_scan<<<NCTA, NTHR>>>(Wh, bh, Wm, bm, out);
}